// round 12
// baseline (speedup 1.0000x reference)
#include <cuda_runtime.h>
#include <cstdint>
#include <cstddef>

// Legacy-path (mma.sync m16n8k8.tf32) fused NeuralCTLSTM, v10:
// 12 warps/CTA (3 per SMSP) AND n16 warp tile AND epilogue staging.
// Fits 227KB smem via: BK=16 k-chunks (A stage 2560B, stride-20 rows,
// conflict-free + 16B-aligned), c/cbar merged per-warp staging buffer
// (36-float rows), dt via early LDG, bias in smem (saves 28 regs).
// Warp-private 2-stage cp.async rings, no loop barriers.
// Grid (16, 9) = 144 CTAs = one wave; 108 warp-streams per o-block.

#define NG 7
#define HH 256
#define BK 16
#define NCHUNK 16
#define THREADS 384
#define GYS 9
#define STREAMS (12 * GYS)                  // 108 warp-streams per o-block

#define OFF_BIAS 0                          // 112 floats + pad = 512B
#define OFF_W 512
#define W_BYTES (NG * NCHUNK * 2 * 512)     // 224 frag-units x 512B = 114688
#define A_P 20                              // A stage row stride (floats)
#define A_STAGE_B (32 * A_P * 4)            // 2560
#define A_WARP_B (2 * A_STAGE_B)            // 5120
#define OFF_A (OFF_W + W_BYTES)             // 115200
#define C_ROW_F 36                          // c[16] + cbar[16] + 4 pad
#define C_ARR_B (32 * C_ROW_F * 4)          // 4608
#define OFF_C (OFF_A + 12 * A_WARP_B)       // 176640
#define SMEM_BYTES (OFF_C + 12 * C_ARR_B)   // 231936

__device__ __forceinline__ uint32_t f2tf32(float f) {
    uint32_t u;
    asm("cvt.rna.tf32.f32 %0, %1;" : "=r"(u) : "f"(f));
    return u;
}

__device__ __forceinline__ void mma_tf32(float* d, const uint32_t* a,
                                         uint32_t b0, uint32_t b1) {
    asm volatile(
        "mma.sync.aligned.m16n8k8.row.col.f32.tf32.tf32.f32 "
        "{%0,%1,%2,%3}, {%4,%5,%6,%7}, {%8,%9}, {%0,%1,%2,%3};\n"
        : "+f"(d[0]), "+f"(d[1]), "+f"(d[2]), "+f"(d[3])
        : "r"(a[0]), "r"(a[1]), "r"(a[2]), "r"(a[3]), "r"(b0), "r"(b1));
}

__device__ __forceinline__ void cp_async16(uint32_t dst, const void* src) {
    asm volatile("cp.async.cg.shared.global [%0], [%1], 16;\n"
                 :: "r"(dst), "l"(src) : "memory");
}

__device__ __forceinline__ float tanh_fast(float x) {
    float y;
    asm("tanh.approx.f32 %0, %1;" : "=f"(y) : "f"(x));
    return y;
}
__device__ __forceinline__ float sigm(float x) {       // 0.5*tanh(x/2)+0.5
    return fmaf(tanh_fast(0.5f * x), 0.5f, 0.5f);
}

extern "C" __global__ void __launch_bounds__(THREADS, 1)
nctlstm_v10_kernel(const float* __restrict__ inter_times,
                   const float* __restrict__ h_ti,
                   const float* __restrict__ c_ti,
                   const float* __restrict__ cbar,
                   const float* __restrict__ W,
                   const float* __restrict__ bias,
                   float* __restrict__ out,
                   int Btot)
{
    extern __shared__ char smem[];
    const uint32_t sb = (uint32_t)__cvta_generic_to_shared(smem);

    const int tid  = threadIdx.x;
    const int warp = tid >> 5;       // 0..11
    const int lane = tid & 31;
    const int grp  = lane >> 2;      // 0..7
    const int tig  = lane & 3;       // 0..3

    const int o0 = blockIdx.x * 16;
    const int stream = blockIdx.y * 12 + warp;   // 0..107
    const int nblk = Btot >> 5;                  // 2048 32-row blocks

    const float* bias_s = reinterpret_cast<const float*>(smem + OFF_BIAS);
    const uint4* wperm = reinterpret_cast<const uint4*>(smem + OFF_W);
    uint4* wperm_w = reinterpret_cast<uint4*>(smem + OFF_W);
    const uint32_t warpA = sb + OFF_A + (uint32_t)warp * A_WARP_B;
    const float*  warpAf = reinterpret_cast<const float*>(smem + OFF_A + warp * A_WARP_B);
    const uint32_t warpC = sb + OFF_C + (uint32_t)warp * C_ARR_B;
    const float*  c_s  = reinterpret_cast<const float*>(smem + OFF_C + warp * C_ARR_B);

    // ---- warp-private A chunk loader: 32 rows x 16 cols, 4 cp.async/lane ----
    auto load_chunk = [&](int rb, int ch, int s) {
        const uint32_t ab = warpA + (uint32_t)s * A_STAGE_B;
        const float* src = h_ti + ((size_t)rb << 5) * HH + ch * BK;
#pragma unroll
        for (int i = 0; i < 4; i++) {
            const int idx = lane + i * 32;        // 0..127
            const int r = idx >> 2, cg = idx & 3;
            cp_async16(ab + (uint32_t)(r * (A_P * 4) + cg * 16),
                       src + (size_t)r * HH + cg * 4);
        }
        asm volatile("cp.async.commit_group;\n" ::: "memory");
    };

    // ---- epilogue-operand stager (NO commit; joins caller's group) ----
    // merged rows: [c 0..15 | cbar 16..31 | pad], 144B row stride.
    auto load_cblock = [&](int rb) {
        const float* csrc  = c_ti + ((size_t)rb << 5) * HH + o0;
        const float* cbsrc = cbar + ((size_t)rb << 5) * HH + o0;
#pragma unroll
        for (int i = 0; i < 4; i++) {
            const int idx = lane + i * 32;        // 0..127
            const int r = idx >> 2, cg = idx & 3;
            cp_async16(warpC + (uint32_t)(r * (C_ROW_F * 4) + cg * 16),
                       csrc + (size_t)r * HH + cg * 4);
            cp_async16(warpC + (uint32_t)(r * (C_ROW_F * 4) + 64 + cg * 16),
                       cbsrc + (size_t)r * HH + cg * 4);
        }
    };

    // prologue: first two chunks of first block in flight during W permute
    const int rb0 = stream;
    load_chunk(rb0, 0, 0);
    load_chunk(rb0, 1, 1);

    // ---- one-time W permute (224 units, 12 warps cooperate) ----
    // unit u = (g*16 + ch)*2 + nh; lane holds both k8-steps of chunk ch:
    // {W[o][16ch+tig], [+4], [16ch+8+tig], [+12]} rna-rounded to tf32.
    for (int u = warp; u < NG * NCHUNK * 2; u += 12) {
        const int nh = u & 1, ch = (u >> 1) & 15, g = u >> 5;
        const int o = o0 + nh * 8 + grp;
        const float* ws = W + ((size_t)g * HH + o) * HH + ch * BK + tig;
        uint4 v;
        v.x = f2tf32(ws[0]);
        v.y = f2tf32(ws[4]);
        v.z = f2tf32(ws[8]);
        v.w = f2tf32(ws[12]);
        wperm_w[u * 32 + lane] = v;
    }

    // bias -> smem (112 floats)
    if (tid < NG * 16) {
        float* bw = reinterpret_cast<float*>(smem + OFF_BIAS);
        bw[tid] = bias[(size_t)(tid >> 4) * HH + o0 + (tid & 15)];
    }

    __syncthreads();   // W permute + bias visible; only block barrier

    const size_t BHtot = (size_t)Btot * HH;
    int s_cons = 0;

    for (int rb = rb0; rb < nblk; rb += STREAMS) {
        float acc[NG][2][2][4];          // [g][nh][mt][frag]
#pragma unroll
        for (int g = 0; g < NG; g++)
#pragma unroll
            for (int nh = 0; nh < 2; nh++) {
                const float2 bb = *reinterpret_cast<const float2*>(
                    bias_s + g * 16 + nh * 8 + 2 * tig);
#pragma unroll
                for (int mt = 0; mt < 2; mt++) {
                    acc[g][nh][mt][0] = bb.x; acc[g][nh][mt][1] = bb.y;
                    acc[g][nh][mt][2] = bb.x; acc[g][nh][mt][3] = bb.y;
                }
            }

#pragma unroll 1
        for (int ch = 0; ch < NCHUNK; ch++) {
            asm volatile("cp.async.wait_group 1;\n" ::: "memory");

            const float* hs = warpAf + s_cons * (A_STAGE_B / 4);

            // A fragments for both k8-steps of this chunk (16 regs)
            uint32_t a[2][2][4];         // [ks][mt][frag]
#pragma unroll
            for (int ks = 0; ks < 2; ks++) {
                const int kb = ks * 8;
#pragma unroll
                for (int mt = 0; mt < 2; mt++) {
                    const int r = mt * 16 + grp;
                    a[ks][mt][0] = __float_as_uint(hs[r * A_P + kb + tig]);
                    a[ks][mt][1] = __float_as_uint(hs[(r + 8) * A_P + kb + tig]);
                    a[ks][mt][2] = __float_as_uint(hs[r * A_P + kb + tig + 4]);
                    a[ks][mt][3] = __float_as_uint(hs[(r + 8) * A_P + kb + tig + 4]);
                }
            }

            // all LDS from stage s_cons issued: safe to overwrite it.
            // chunk 0 also stages this block's epilogue operands (same group).
            {
                if (ch == 0) load_cblock(rb);
                int c2 = ch + 2, r2 = rb;
                if (c2 >= NCHUNK) { c2 -= NCHUNK; r2 += STREAMS; }
                if (r2 < nblk) load_chunk(r2, c2, s_cons);
                else           asm volatile("cp.async.commit_group;\n" ::: "memory");
            }
            s_cons ^= 1;

            // 14 LDS.128 (W frags) + 56 HMMA
#pragma unroll
            for (int g = 0; g < NG; g++) {
#pragma unroll
                for (int nh = 0; nh < 2; nh++) {
                    const uint4 wf = wperm[(((g * 16 + ch) * 2) + nh) * 32 + lane];
                    mma_tf32(acc[g][nh][0], a[0][0], wf.x, wf.y);
                    mma_tf32(acc[g][nh][1], a[0][1], wf.x, wf.y);
                    mma_tf32(acc[g][nh][0], a[1][0], wf.z, wf.w);
                    mma_tf32(acc[g][nh][1], a[1][1], wf.z, wf.w);
                }
            }
        }

        // ---- fused epilogue: c/cbar from smem; dt via early LDG ----
        float dtv[2][2];
#pragma unroll
        for (int mt = 0; mt < 2; mt++)
#pragma unroll
            for (int rs = 0; rs < 2; rs++)
                dtv[mt][rs] = __ldg(inter_times + rb * 32 + mt * 16 + grp + rs * 8);

#pragma unroll
        for (int mt = 0; mt < 2; mt++) {
#pragma unroll
            for (int rs = 0; rs < 2; rs++) {
                const int row = mt * 16 + grp + rs * 8;       // 0..31
                const int b = rb * 32 + row;
                const float dt = dtv[mt][rs];
#pragma unroll
                for (int nh = 0; nh < 2; nh++) {
                    const int col = nh * 8 + 2 * tig;
                    const float2 cv = *reinterpret_cast<const float2*>(
                        c_s + row * C_ROW_F + col);
                    const float2 cb = *reinterpret_cast<const float2*>(
                        c_s + row * C_ROW_F + 16 + col);
                    const size_t base = (size_t)b * HH + o0 + col;

                    float2 r_o, r_h, r_c, r_cb, r_d;
#pragma unroll
                    for (int j = 0; j < 2; j++) {
                        const int ai = rs * 2 + j;
                        const float gi  = acc[0][nh][mt][ai];
                        const float gf  = acc[1][nh][mt][ai];
                        const float go  = acc[2][nh][mt][ai];
                        const float gib = acc[3][nh][mt][ai];
                        const float gfb = acc[4][nh][mt][ai];
                        const float gz  = acc[5][nh][mt][ai];
                        const float gd  = acc[6][nh][mt][ai];

                        const float i_g  = sigm(gi);
                        const float f_g  = sigm(gf);
                        const float o_g  = sigm(go);
                        const float ib_g = sigm(gib);
                        const float fb_g = sigm(gfb);
                        const float z    = tanh_fast(gz);
                        const float decay = fmaxf(gd, 0.0f)
                                          + __logf(1.0f + __expf(-fabsf(gd)));

                        const float ct  = (j == 0) ? cv.x : cv.y;
                        const float cbv = (j == 0) ? cb.x : cb.y;

                        const float e       = __expf(-decay * dt);
                        const float c_after = cbv + (ct - cbv) * e;
                        const float c_new   = f_g * c_after + i_g * z;
                        const float cb_new  = fb_g * cbv + ib_g * z;
                        const float h_new   = o_g * tanh_fast(c_after);

                        if (j == 0) { r_o.x = o_g; r_h.x = h_new; r_c.x = c_new; r_cb.x = cb_new; r_d.x = decay; }
                        else        { r_o.y = o_g; r_h.y = h_new; r_c.y = c_new; r_cb.y = cb_new; r_d.y = decay; }
                    }
                    __stcs(reinterpret_cast<float2*>(out + 0 * BHtot + base), r_o);
                    __stcs(reinterpret_cast<float2*>(out + 1 * BHtot + base), r_h);
                    __stcs(reinterpret_cast<float2*>(out + 2 * BHtot + base), r_c);
                    __stcs(reinterpret_cast<float2*>(out + 3 * BHtot + base), r_cb);
                    __stcs(reinterpret_cast<float2*>(out + 4 * BHtot + base), r_d);
                }
            }
        }
    }
}

extern "C" void kernel_launch(void* const* d_in, const int* in_sizes, int n_in,
                              void* d_out, int out_size)
{
    const float* inter_times = (const float*)d_in[0];
    const float* h_ti        = (const float*)d_in[1];
    const float* c_ti        = (const float*)d_in[2];
    const float* cbar        = (const float*)d_in[3];
    const float* W           = (const float*)d_in[4];
    const float* bias        = (const float*)d_in[5];
    const int B = in_sizes[0];

    cudaFuncSetAttribute(nctlstm_v10_kernel,
                         cudaFuncAttributeMaxDynamicSharedMemorySize, SMEM_BYTES);

    dim3 grid(16, GYS);   // 144 CTAs = one wave; one 16-col o-block per CTA
    nctlstm_v10_kernel<<<grid, THREADS, SMEM_BYTES>>>(
        inter_times, h_ti, c_ti, cbar, W, bias, (float*)d_out, B);
}